// round 3
// baseline (speedup 1.0000x reference)
#include <cuda_runtime.h>
#include <math.h>

// Problem constants
#define B_   4
#define U_   8192
#define E_   128
#define GH_  64
#define GW_  64
#define S_   (GH_*GW_)        // 4096
#define NB_  (B_*S_)          // 16384 buckets
#define NOFF (B_*U_)          // 32768 off-grid tokens
#define CAP_ 23               // MAX_PATCH-1 usable slots
#define MAXP 24

// ---------------- scratch (device globals; no cudaMalloc allowed) ----------
__device__ float g_Koff[NOFF*E_];   // 16 MB
__device__ float g_Voff[NOFF*E_];   // 16 MB
__device__ float g_Kon [NB_*E_];    // 8 MB
__device__ float g_Von [NB_*E_];    // 8 MB
__device__ float g_Q   [S_*E_];     // 2 MB (shared across batch)
__device__ float g_attn[NB_*E_];    // 8 MB
__device__ int   g_counts[NB_];
__device__ int   g_members[NB_*CAP_];
__device__ float g_Kfake[E_];
__device__ float g_Vfake[E_];

// ---------------- f32x2 helpers --------------------------------------------
__device__ __forceinline__ void fma2(unsigned long long &d,
                                     unsigned long long a,
                                     unsigned long long b) {
    asm("fma.rn.f32x2 %0, %1, %2, %0;" : "+l"(d) : "l"(a), "l"(b));
}
__device__ __forceinline__ unsigned long long pack2(float a) {
    unsigned long long r;
    asm("mov.b64 %0, {%1, %1};" : "=l"(r) : "f"(a));
    return r;
}

// ---------------- Stage 1: bucket assignment --------------------------------
__global__ void bucket_kernel(const float* __restrict__ xoff,
                              const float* __restrict__ xon) {
    int i = blockIdx.x * blockDim.x + threadIdx.x;
    if (i >= NOFF) return;
    // axis values straight from the input grid (exact match to reference)
    float ay0 = xon[0];           // x_grid[0,0,0,0]
    float ay1 = xon[2*GW_];       // x_grid[0,1,0,0]
    float ax0 = xon[1];           // x_grid[0,0,0,1]
    float ax1 = xon[3];           // x_grid[0,0,1,1]
    float sy = ay1 - ay0;
    float sx = ax1 - ax0;
    float x0 = xoff[2*i+0];
    float x1 = xoff[2*i+1];
    // IEEE-correct div + round-half-even, matching jnp semantics exactly
    float r0 = rintf(__fdiv_rn(x0 - ay0, sy));
    float r1 = rintf(__fdiv_rn(x1 - ax0, sx));
    int i0 = (int)fminf(fmaxf(r0, 0.0f), (float)(GH_-1));
    int i1 = (int)fminf(fmaxf(r1, 0.0f), (float)(GW_-1));
    int b  = i / U_;
    int flat = b * S_ + i0 * GW_ + i1;
    int slot = atomicAdd(&g_counts[flat], 1);
    if (slot < CAP_) g_members[flat*CAP_ + slot] = i;
}

// ---------------- Stage 2: fp32 GEMM  C[M,128] = A[M,128] @ W[128,128] ------
// Block tile 64x128, K-chunks of 32, thread micro-tile 4(M) x 8(N),
// accumulators packed as f32x2 pairs along N (b-operands load packed from smem).
__global__ void __launch_bounds__(256) gemm_rm128(const float* __restrict__ A,
                                                  const float* __restrict__ W,
                                                  float* __restrict__ C) {
    __shared__ float As[64][33];      // 64 rows x 32 k (pad->33, conflict-free)
    __shared__ float Ws[32][128];     // k-chunk of W
    const int tid = threadIdx.x;
    const int tx  = tid & 15;         // n: n0 = tx*8
    const int ty  = tid >> 4;         // m: m0 = ty*4
    const int rowBase = blockIdx.x * 64;

    unsigned long long acc[4][4];
#pragma unroll
    for (int i = 0; i < 4; i++)
#pragma unroll
        for (int j = 0; j < 4; j++) acc[i][j] = 0ull;

    for (int kc = 0; kc < 128; kc += 32) {
        // load A tile chunk: 64 rows x 32 floats
#pragma unroll
        for (int r = 0; r < 2; r++) {
            int row = (tid >> 3) + 32 * r;
            int kq  = (tid & 7) * 4;
            float4 v = *(const float4*)&A[(rowBase + row) * 128 + kc + kq];
            As[row][kq+0] = v.x;
            As[row][kq+1] = v.y;
            As[row][kq+2] = v.z;
            As[row][kq+3] = v.w;
        }
        // load W chunk: contiguous 32x128 block
        {
            const float4* Wg = (const float4*)&W[kc * 128];
            float4* Wsv = (float4*)&Ws[0][0];
#pragma unroll
            for (int r = 0; r < 4; r++) Wsv[tid + 256*r] = Wg[tid + 256*r];
        }
        __syncthreads();

#pragma unroll 8
        for (int k = 0; k < 32; k++) {
            ulonglong2 b0 = *(const ulonglong2*)&Ws[k][tx*8];
            ulonglong2 b1 = *(const ulonglong2*)&Ws[k][tx*8 + 4];
#pragma unroll
            for (int i = 0; i < 4; i++) {
                unsigned long long ap = pack2(As[ty*4 + i][k]);
                fma2(acc[i][0], ap, b0.x);
                fma2(acc[i][1], ap, b0.y);
                fma2(acc[i][2], ap, b1.x);
                fma2(acc[i][3], ap, b1.y);
            }
        }
        __syncthreads();
    }
#pragma unroll
    for (int i = 0; i < 4; i++) {
        int off = (rowBase + ty*4 + i) * 128 + tx*8;
        *(ulonglong2*)&C[off]     = make_ulonglong2(acc[i][0], acc[i][1]);
        *(ulonglong2*)&C[off + 4] = make_ulonglong2(acc[i][2], acc[i][3]);
    }
}

// ---------------- Stage 3: fake-embedding projection ------------------------
__global__ void fake_proj(const float* __restrict__ fake,
                          const float* __restrict__ Wk,
                          const float* __restrict__ Wv) {
    __shared__ float f[E_];
    int t = threadIdx.x;
    f[t] = fake[t];
    __syncthreads();
    float sk = 0.f, sv = 0.f;
#pragma unroll 8
    for (int k = 0; k < E_; k++) {
        sk += f[k] * Wk[k*E_ + t];
        sv += f[k] * Wv[k*E_ + t];
    }
    g_Kfake[t] = sk;
    g_Vfake[t] = sv;
}

// ---------------- Stage 4: per-bucket attention (1 warp / bucket) -----------
__global__ void __launch_bounds__(128) attn_kernel(const int* __restrict__ ign_p) {
    __shared__ int mem[4][CAP_];
    const int warp = threadIdx.x >> 5;
    const int lane = threadIdx.x & 31;
    const int n = blockIdx.x * 4 + warp;
    const int ign = *ign_p;

    int c = min(g_counts[n], CAP_);
    if (lane < c) mem[warp][lane] = g_members[n*CAP_ + lane];
    __syncwarp();
    if (lane == 0 && c > 1) {           // deterministic order (matches original)
        int* a = mem[warp];
        for (int i = 1; i < c; i++) {
            int key = a[i]; int j = i - 1;
            while (j >= 0 && a[j] > key) { a[j+1] = a[j]; j--; }
            a[j+1] = key;
        }
    }
    __syncwarp();

    const int s = n & (S_ - 1);
    float4 q = *(const float4*)&g_Q[s*E_ + lane*4];

    float m = -INFINITY, lsum = 0.f;
    float4 acc = make_float4(0.f, 0.f, 0.f, 0.f);

    for (int p = 0; p <= c; p++) {
        const float *kr, *vr;
        if (p < c) {
            int t = mem[warp][p];
            kr = &g_Koff[t * E_];
            vr = &g_Voff[t * E_];
        } else if (!ign) {
            kr = &g_Kon[n * E_];
            vr = &g_Von[n * E_];
        } else {
            kr = g_Kfake;
            vr = g_Vfake;
        }
        float4 kk = *(const float4*)&kr[lane*4];
        float d = q.x*kk.x + q.y*kk.y + q.z*kk.z + q.w*kk.w;
        d += __shfl_xor_sync(0xffffffffu, d, 1);
        d += __shfl_xor_sync(0xffffffffu, d, 2);   // head-group (4 lanes) sum
        float sc = d * 0.25f;                      // 1/sqrt(DH=16)
        float mn = fmaxf(m, sc);
        float corr = expf(m - mn);
        float w = expf(sc - mn);
        lsum = lsum * corr + w;
        float4 vv = *(const float4*)&vr[lane*4];
        acc.x = acc.x*corr + w*vv.x;
        acc.y = acc.y*corr + w*vv.y;
        acc.z = acc.z*corr + w*vv.z;
        acc.w = acc.w*corr + w*vv.w;
        m = mn;
    }
    float inv = 1.0f / lsum;
    float4 o = make_float4(acc.x*inv, acc.y*inv, acc.z*inv, acc.w*inv);
    *(float4*)&g_attn[n*E_ + lane*4] = o;
}

// ---------------- launcher ---------------------------------------------------
extern "C" void kernel_launch(void* const* d_in, const int* in_sizes, int n_in,
                              void* d_out, int out_size) {
    const float* xoff = (const float*)d_in[0];   // (B,U,2)
    const float* xon  = (const float*)d_in[1];   // (B,GH,GW,2)
    const float* zoff = (const float*)d_in[2];   // (B,U,E)
    const float* zon  = (const float*)d_in[3];   // (B,GH,GW,E)
    const float* lat  = (const float*)d_in[4];   // (GH,GW,E)
    const float* fake = (const float*)d_in[5];   // (E,)
    const float* Wq   = (const float*)d_in[6];
    const float* Wk   = (const float*)d_in[7];
    const float* Wv   = (const float*)d_in[8];
    const float* Wo   = (const float*)d_in[9];
    const int*   ign  = (const int*)d_in[10];
    float* out = (float*)d_out;

    float *pKoff, *pVoff, *pKon, *pVon, *pQ, *pAttn;
    int* pCounts;
    cudaGetSymbolAddress((void**)&pKoff, g_Koff);
    cudaGetSymbolAddress((void**)&pVoff, g_Voff);
    cudaGetSymbolAddress((void**)&pKon,  g_Kon);
    cudaGetSymbolAddress((void**)&pVon,  g_Von);
    cudaGetSymbolAddress((void**)&pQ,    g_Q);
    cudaGetSymbolAddress((void**)&pAttn, g_attn);
    cudaGetSymbolAddress((void**)&pCounts, g_counts);

    cudaMemsetAsync(pCounts, 0, NB_ * sizeof(int));
    bucket_kernel<<<(NOFF + 255) / 256, 256>>>(xoff, xon);

    gemm_rm128<<<NOFF / 64, 256>>>(zoff, Wk, pKoff);
    gemm_rm128<<<NOFF / 64, 256>>>(zoff, Wv, pVoff);
    gemm_rm128<<<NB_  / 64, 256>>>(zon,  Wk, pKon);
    gemm_rm128<<<NB_  / 64, 256>>>(zon,  Wv, pVon);
    gemm_rm128<<<S_   / 64, 256>>>(lat,  Wq, pQ);
    fake_proj<<<1, 128>>>(fake, Wk, Wv);

    attn_kernel<<<NB_ / 4, 128>>>(ign);

    gemm_rm128<<<NB_ / 64, 256>>>(pAttn, Wo, out);
}

// round 5
// speedup vs baseline: 2.0994x; 2.0994x over previous
#include <cuda_runtime.h>
#include <cuda_bf16.h>
#include <math.h>
#include <stdint.h>

// Problem constants
#define B_   4
#define U_   8192
#define E_   128
#define GH_  64
#define GW_  64
#define S_   (GH_*GW_)        // 4096
#define NB_  (B_*S_)          // 16384 buckets
#define NOFF (B_*U_)          // 32768 off-grid tokens
#define CAP_ 23               // MAX_PATCH-1 usable slots

// ---------------- scratch (device globals; no cudaMalloc allowed) ----------
__device__ float g_Koff[NOFF*E_];   // 16 MB
__device__ float g_Voff[NOFF*E_];   // 16 MB
__device__ float g_Kon [NB_*E_];    // 8 MB
__device__ float g_Von [NB_*E_];    // 8 MB
__device__ float g_Q   [S_*E_];     // 2 MB (shared across batch)
__device__ float g_attn[NB_*E_];    // 8 MB
__device__ int   g_counts[NB_];
__device__ int   g_members[NB_*CAP_];
__device__ float g_Kfake[E_];
__device__ float g_Vfake[E_];
// Pre-split bf16 weights, transposed + k-pair-packed for the mma B fragment:
// g_Wp[w][p][kk*128 + n] = bf16(W[2kk][n]) | bf16(W[2kk+1][n])<<16
// w: 0=Wq 1=Wk 2=Wv 3=Wo ; p: 0=hi 1=lo(residual)
__device__ uint32_t g_Wp[4][2][64*128];

// ---------------- helpers ----------------------------------------------------
__device__ __forceinline__ uint32_t pk2(float x, float y) {
    uint32_t lo = (uint32_t)__bfloat16_as_ushort(__float2bfloat16(x));
    uint32_t hi = (uint32_t)__bfloat16_as_ushort(__float2bfloat16(y));
    return lo | (hi << 16);
}
__device__ __forceinline__ float resid(float x) {
    return x - __bfloat162float(__float2bfloat16(x));
}
__device__ __forceinline__ void mma16816(float* c, const uint32_t* a,
                                         uint32_t b0, uint32_t b1) {
    asm volatile(
        "mma.sync.aligned.m16n8k16.row.col.f32.bf16.bf16.f32 "
        "{%0,%1,%2,%3}, {%4,%5,%6,%7}, {%8,%9}, {%0,%1,%2,%3};"
        : "+f"(c[0]), "+f"(c[1]), "+f"(c[2]), "+f"(c[3])
        : "r"(a[0]), "r"(a[1]), "r"(a[2]), "r"(a[3]), "r"(b0), "r"(b1));
}

// ---------------- Stage 0: split/pack the four weights ----------------------
__global__ void wsplit_kernel(const float* __restrict__ Wq,
                              const float* __restrict__ Wk,
                              const float* __restrict__ Wv,
                              const float* __restrict__ Wo) {
    const float* W = (blockIdx.x == 0) ? Wq : (blockIdx.x == 1) ? Wk
                   : (blockIdx.x == 2) ? Wv : Wo;
    uint32_t* dh = g_Wp[blockIdx.x][0];
    uint32_t* dl = g_Wp[blockIdx.x][1];
    for (int idx = threadIdx.x; idx < 64 * 128; idx += blockDim.x) {
        int kk = idx >> 7;         // k pair index
        int n  = idx & 127;
        float w0 = W[(2*kk)   * 128 + n];
        float w1 = W[(2*kk+1) * 128 + n];
        dh[idx] = pk2(w0, w1);
        dl[idx] = pk2(resid(w0), resid(w1));
    }
}

// ---------------- Stage 1: bucket assignment --------------------------------
__global__ void bucket_kernel(const float* __restrict__ xoff,
                              const float* __restrict__ xon) {
    int i = blockIdx.x * blockDim.x + threadIdx.x;
    if (i >= NOFF) return;
    float ay0 = xon[0];
    float ay1 = xon[2*GW_];
    float ax0 = xon[1];
    float ax1 = xon[3];
    float x0 = xoff[2*i+0];
    float x1 = xoff[2*i+1];
    float r0 = rintf(__fdiv_rn(x0 - ay0, ay1 - ay0));
    float r1 = rintf(__fdiv_rn(x1 - ax0, ax1 - ax0));
    int i0 = (int)fminf(fmaxf(r0, 0.0f), (float)(GH_-1));
    int i1 = (int)fminf(fmaxf(r1, 0.0f), (float)(GW_-1));
    int flat = (i / U_) * S_ + i0 * GW_ + i1;
    int slot = atomicAdd(&g_counts[flat], 1);
    if (slot < CAP_) g_members[flat*CAP_ + slot] = i;
}

// ---------------- Stage 2: bf16-split HMMA GEMM  C[64,128] per CTA ----------
// D = Ah*Wh + Ah*Wl + Al*Wh, accumulated fp32 in mma.sync.m16n8k16.
// smem: W hi/lo as u32 [64 rows][136 words] (pad => conflict-free B LDS).
#define WROW 136
#define SM_WORDS (2 * 64 * WROW)          // 17408 u32 = 69632 B
#define DSMEM_BYTES (SM_WORDS * 4)

__global__ void __launch_bounds__(256) gemm_mma(const float* __restrict__ zoff,
                                                const float* __restrict__ zon,
                                                const float* __restrict__ lat,
                                                const float* __restrict__ attnA,
                                                float* __restrict__ outC,
                                                int phase) {
    extern __shared__ uint32_t sw[];       // [0..8703]=hi, [8704..]=lo
    const int tid = threadIdx.x;
    const int blk = blockIdx.x;

    // ---- job decode (64 rows per CTA) ----
    int wsel;
    const float* A;
    float* C;
    if (phase) {
        wsel = 3; A = attnA + (size_t)blk * 64 * E_; C = outC + (size_t)blk * 64 * E_;
    } else if (blk < 512) {
        wsel = 1; A = zoff + (size_t)blk * 64 * E_;        C = g_Koff + (size_t)blk * 64 * E_;
    } else if (blk < 1024) {
        wsel = 2; A = zoff + (size_t)(blk-512) * 64 * E_;  C = g_Voff + (size_t)(blk-512) * 64 * E_;
    } else if (blk < 1280) {
        wsel = 1; A = zon + (size_t)(blk-1024) * 64 * E_;  C = g_Kon + (size_t)(blk-1024) * 64 * E_;
    } else if (blk < 1536) {
        wsel = 2; A = zon + (size_t)(blk-1280) * 64 * E_;  C = g_Von + (size_t)(blk-1280) * 64 * E_;
    } else {
        wsel = 0; A = lat + (size_t)(blk-1536) * 64 * E_;  C = g_Q + (size_t)(blk-1536) * 64 * E_;
    }

    // ---- load packed W hi/lo into padded smem ----
    {
        const float4* srcH = (const float4*)g_Wp[wsel][0];
        const float4* srcL = (const float4*)g_Wp[wsel][1];
#pragma unroll
        for (int i = tid; i < 2048; i += 256) {
            int row = i >> 5;            // 0..63
            int c4  = i & 31;            // float4 within row
            *(float4*)&sw[row*WROW + c4*4]        = srcH[i];
            *(float4*)&sw[8704 + row*WROW + c4*4] = srcL[i];
        }
    }
    __syncthreads();

    // ---- warp tiling: 8 warps = 4 (M) x 2 (N); warp tile 16x64 ----
    const int wid  = tid >> 5;
    const int lane = tid & 31;
    const int m0 = (wid & 3) * 16;
    const int n0 = (wid >> 2) * 64;
    const int g = lane >> 2;             // 0..7
    const int c = lane & 3;              // 0..3

    float acc[8][4];
#pragma unroll
    for (int i = 0; i < 8; i++)
#pragma unroll
        for (int j = 0; j < 4; j++) acc[i][j] = 0.f;

#pragma unroll
    for (int kc = 0; kc < 8; kc++) {
        const int k0 = kc * 16;
        const float* ar = A + (m0 + g) * E_ + k0 + 2*c;
        float2 x0 = *(const float2*)ar;
        float2 x1 = *(const float2*)(ar + 8*E_);
        float2 x2 = *(const float2*)(ar + 8);
        float2 x3 = *(const float2*)(ar + 8*E_ + 8);
        uint32_t ah[4], al[4];
        ah[0] = pk2(x0.x, x0.y);  al[0] = pk2(resid(x0.x), resid(x0.y));
        ah[1] = pk2(x1.x, x1.y);  al[1] = pk2(resid(x1.x), resid(x1.y));
        ah[2] = pk2(x2.x, x2.y);  al[2] = pk2(resid(x2.x), resid(x2.y));
        ah[3] = pk2(x3.x, x3.y);  al[3] = pk2(resid(x3.x), resid(x3.y));

        const int brow = kc * 8 + c;
#pragma unroll
        for (int nt = 0; nt < 8; nt++) {
            int col = n0 + nt*8 + g;
            uint32_t bh0 = sw[brow*WROW + col];
            uint32_t bh1 = sw[(brow+4)*WROW + col];
            uint32_t bl0 = sw[8704 + brow*WROW + col];
            uint32_t bl1 = sw[8704 + (brow+4)*WROW + col];
            mma16816(acc[nt], ah, bh0, bh1);
            mma16816(acc[nt], ah, bl0, bl1);
            mma16816(acc[nt], al, bh0, bh1);
        }
    }

    // ---- epilogue ----
#pragma unroll
    for (int nt = 0; nt < 8; nt++) {
        int colb = n0 + nt*8 + 2*c;
        *(float2*)&C[(m0 + g) * E_ + colb]     = make_float2(acc[nt][0], acc[nt][1]);
        *(float2*)&C[(m0 + g + 8) * E_ + colb] = make_float2(acc[nt][2], acc[nt][3]);
    }
}

// ---------------- Stage 3: fake-embedding projection ------------------------
__global__ void fake_proj(const float* __restrict__ fake,
                          const float* __restrict__ Wk,
                          const float* __restrict__ Wv) {
    __shared__ float f[E_];
    int t = threadIdx.x;
    f[t] = fake[t];
    __syncthreads();
    float sk = 0.f, sv = 0.f;
#pragma unroll 8
    for (int k = 0; k < E_; k++) {
        sk += f[k] * Wk[k*E_ + t];
        sv += f[k] * Wv[k*E_ + t];
    }
    g_Kfake[t] = sk;
    g_Vfake[t] = sv;
}

// ---------------- Stage 4: per-bucket attention (1 warp / bucket) -----------
__global__ void __launch_bounds__(128) attn_kernel(const int* __restrict__ ign_p) {
    __shared__ int mem[4][CAP_];
    const int warp = threadIdx.x >> 5;
    const int lane = threadIdx.x & 31;
    const int n = blockIdx.x * 4 + warp;
    const int ign = *ign_p;

    int c = min(g_counts[n], CAP_);
    if (lane < c) mem[warp][lane] = g_members[n*CAP_ + lane];
    __syncwarp();
    if (lane == 0 && c > 1) {           // deterministic order
        int* a = mem[warp];
        for (int i = 1; i < c; i++) {
            int key = a[i]; int j = i - 1;
            while (j >= 0 && a[j] > key) { a[j+1] = a[j]; j--; }
            a[j+1] = key;
        }
    }
    __syncwarp();

    const int s = n & (S_ - 1);
    float4 q = *(const float4*)&g_Q[s*E_ + lane*4];

    float m = -INFINITY, lsum = 0.f;
    float4 acc = make_float4(0.f, 0.f, 0.f, 0.f);

    for (int p = 0; p <= c; p++) {
        const float *kr, *vr;
        if (p < c) {
            int t = mem[warp][p];
            kr = &g_Koff[t * E_];
            vr = &g_Voff[t * E_];
        } else if (!ign) {
            kr = &g_Kon[n * E_];
            vr = &g_Von[n * E_];
        } else {
            kr = g_Kfake;
            vr = g_Vfake;
        }
        float4 kk = *(const float4*)&kr[lane*4];
        float d = q.x*kk.x + q.y*kk.y + q.z*kk.z + q.w*kk.w;
        d += __shfl_xor_sync(0xffffffffu, d, 1);
        d += __shfl_xor_sync(0xffffffffu, d, 2);   // head-group (4 lanes) sum
        float sc = d * 0.25f;                      // 1/sqrt(DH=16)
        float mn = fmaxf(m, sc);
        float corr = expf(m - mn);
        float w = expf(sc - mn);
        lsum = lsum * corr + w;
        float4 vv = *(const float4*)&vr[lane*4];
        acc.x = acc.x*corr + w*vv.x;
        acc.y = acc.y*corr + w*vv.y;
        acc.z = acc.z*corr + w*vv.z;
        acc.w = acc.w*corr + w*vv.w;
        m = mn;
    }
    float inv = 1.0f / lsum;
    float4 o = make_float4(acc.x*inv, acc.y*inv, acc.z*inv, acc.w*inv);
    *(float4*)&g_attn[n*E_ + lane*4] = o;
}

// ---------------- launcher ---------------------------------------------------
extern "C" void kernel_launch(void* const* d_in, const int* in_sizes, int n_in,
                              void* d_out, int out_size) {
    const float* xoff = (const float*)d_in[0];
    const float* xon  = (const float*)d_in[1];
    const float* zoff = (const float*)d_in[2];
    const float* zon  = (const float*)d_in[3];
    const float* lat  = (const float*)d_in[4];
    const float* fake = (const float*)d_in[5];
    const float* Wq   = (const float*)d_in[6];
    const float* Wk   = (const float*)d_in[7];
    const float* Wv   = (const float*)d_in[8];
    const float* Wo   = (const float*)d_in[9];
    const int*   ign  = (const int*)d_in[10];
    float* out = (float*)d_out;

    float* pAttn;
    int* pCounts;
    cudaGetSymbolAddress((void**)&pAttn, g_attn);
    cudaGetSymbolAddress((void**)&pCounts, g_counts);

    cudaFuncSetAttribute(gemm_mma,
                         cudaFuncAttributeMaxDynamicSharedMemorySize, DSMEM_BYTES);

    cudaMemsetAsync(pCounts, 0, NB_ * sizeof(int));
    wsplit_kernel<<<4, 256>>>(Wq, Wk, Wv, Wo);
    bucket_kernel<<<(NOFF + 255) / 256, 256>>>(xoff, xon);

    // fused K/V/Q projections: 1600 CTAs of 64 rows each
    gemm_mma<<<1600, 256, DSMEM_BYTES>>>(zoff, zon, lat, nullptr, nullptr, 0);
    fake_proj<<<1, 128>>>(fake, Wk, Wv);

    attn_kernel<<<NB_ / 4, 128>>>(ign);

    // output projection: attn @ Wo -> out (256 CTAs)
    gemm_mma<<<256, 256, DSMEM_BYTES>>>(nullptr, nullptr, nullptr, pAttn, out, 1);
}

// round 6
// speedup vs baseline: 2.5918x; 1.2345x over previous
#include <cuda_runtime.h>
#include <cuda_bf16.h>
#include <math.h>
#include <stdint.h>

// Problem constants
#define B_   4
#define U_   8192
#define E_   128
#define GH_  64
#define GW_  64
#define S_   (GH_*GW_)        // 4096
#define NB_  (B_*S_)          // 16384 buckets
#define NOFF (B_*U_)          // 32768 off-grid tokens
#define CAP_ 23               // MAX_PATCH-1 usable slots

// ---------------- scratch (device globals; no cudaMalloc allowed) ----------
__device__ float g_Koff[NOFF*E_];   // 16 MB
__device__ float g_Voff[NOFF*E_];   // 16 MB
__device__ float g_Kon [NB_*E_];    // 8 MB
__device__ float g_Von [NB_*E_];    // 8 MB
__device__ float g_Q   [S_*E_];     // 2 MB (shared across batch)
__device__ float g_attn[NB_*E_];    // 8 MB
__device__ int   g_counts[NB_];
__device__ int   g_members[NB_*CAP_];
__device__ float g_Kfake[E_];
__device__ float g_Vfake[E_];
// Pre-split bf16 weights, transposed + k-pair-packed for the mma B fragment:
// g_Wp[w][p][kk*128 + n] = bf16(W[2kk][n]) | bf16(W[2kk+1][n])<<16
// w: 0=Wq 1=Wk 2=Wv 3=Wo ; p: 0=hi 1=lo(residual)
__device__ uint32_t g_Wp[4][2][64*128];

// ---------------- helpers ----------------------------------------------------
__device__ __forceinline__ uint32_t pk2(float x, float y) {
    uint32_t lo = (uint32_t)__bfloat16_as_ushort(__float2bfloat16(x));
    uint32_t hi = (uint32_t)__bfloat16_as_ushort(__float2bfloat16(y));
    return lo | (hi << 16);
}
__device__ __forceinline__ float resid(float x) {
    return x - __bfloat162float(__float2bfloat16(x));
}
__device__ __forceinline__ void mma16816(float* c, const uint32_t* a,
                                         uint32_t b0, uint32_t b1) {
    asm volatile(
        "mma.sync.aligned.m16n8k16.row.col.f32.bf16.bf16.f32 "
        "{%0,%1,%2,%3}, {%4,%5,%6,%7}, {%8,%9}, {%0,%1,%2,%3};"
        : "+f"(c[0]), "+f"(c[1]), "+f"(c[2]), "+f"(c[3])
        : "r"(a[0]), "r"(a[1]), "r"(a[2]), "r"(a[3]), "r"(b0), "r"(b1));
}

// ---------------- Stage 1 (fused prep): wsplit + bucketize + fake proj ------
// blocks 0..3    : split/pack weight blockIdx.x
// blocks 4..131  : bucket assignment for off-grid points
// blocks 132..139: fake-embedding K/V projection (64 warps, 4 outputs each)
__global__ void __launch_bounds__(256) prep_kernel(const float* __restrict__ Wq,
                                                   const float* __restrict__ Wk,
                                                   const float* __restrict__ Wv,
                                                   const float* __restrict__ Wo,
                                                   const float* __restrict__ xoff,
                                                   const float* __restrict__ xon,
                                                   const float* __restrict__ fake) {
    const int blk = blockIdx.x;
    const int tid = threadIdx.x;

    if (blk < 4) {
        // ---- weight split/pack ----
        const float* W = (blk == 0) ? Wq : (blk == 1) ? Wk : (blk == 2) ? Wv : Wo;
        uint32_t* dh = g_Wp[blk][0];
        uint32_t* dl = g_Wp[blk][1];
        for (int idx = tid; idx < 64 * 128; idx += 256) {
            int kk = idx >> 7;
            int n  = idx & 127;
            float w0 = W[(2*kk)   * 128 + n];
            float w1 = W[(2*kk+1) * 128 + n];
            dh[idx] = pk2(w0, w1);
            dl[idx] = pk2(resid(w0), resid(w1));
        }
    } else if (blk < 132) {
        // ---- bucket assignment ----
        int i = (blk - 4) * 256 + tid;
        float ay0 = xon[0];
        float ay1 = xon[2*GW_];
        float ax0 = xon[1];
        float ax1 = xon[3];
        float x0 = xoff[2*i+0];
        float x1 = xoff[2*i+1];
        float r0 = rintf(__fdiv_rn(x0 - ay0, ay1 - ay0));
        float r1 = rintf(__fdiv_rn(x1 - ax0, ax1 - ax0));
        int i0 = (int)fminf(fmaxf(r0, 0.0f), (float)(GH_-1));
        int i1 = (int)fminf(fmaxf(r1, 0.0f), (float)(GW_-1));
        int flat = (i / U_) * S_ + i0 * GW_ + i1;
        int slot = atomicAdd(&g_counts[flat], 1);
        if (slot < CAP_) g_members[flat*CAP_ + slot] = i;
    } else {
        // ---- fake projection: 8 blocks x 8 warps = 64 warps, 4 outputs each
        const int wid  = tid >> 5;
        const int lane = tid & 31;
        const int fw = (blk - 132) * 8 + wid;      // 0..63
        float f0 = fake[lane];
        float f1 = fake[lane + 32];
        float f2 = fake[lane + 64];
        float f3 = fake[lane + 96];
#pragma unroll
        for (int t = 0; t < 4; t++) {
            int o = fw * 4 + t;                    // 0..255
            int col = o & 127;
            const float* W = (o < 128) ? Wk : Wv;
            float s = f0 * W[lane*128 + col]
                    + f1 * W[(lane+32)*128 + col]
                    + f2 * W[(lane+64)*128 + col]
                    + f3 * W[(lane+96)*128 + col];
#pragma unroll
            for (int d = 16; d > 0; d >>= 1)
                s += __shfl_xor_sync(0xffffffffu, s, d);
            if (lane == 0) {
                if (o < 128) g_Kfake[col] = s;
                else         g_Vfake[col] = s;
            }
        }
    }
}

// ---------------- Stage 2: bf16-split HMMA GEMM  C[64,128] per CTA ----------
// D = Ah*Wh + Ah*Wl + Al*Wh, accumulated fp32 in mma.sync.m16n8k16.
#define WROW 136
#define SM_WORDS (2 * 64 * WROW)          // 17408 u32 = 69632 B
#define DSMEM_BYTES (SM_WORDS * 4)

__global__ void __launch_bounds__(256) gemm_mma(const float* __restrict__ zoff,
                                                const float* __restrict__ zon,
                                                const float* __restrict__ lat,
                                                const float* __restrict__ attnA,
                                                float* __restrict__ outC,
                                                int phase) {
    extern __shared__ uint32_t sw[];       // [0..8703]=hi, [8704..]=lo
    const int tid = threadIdx.x;
    const int blk = blockIdx.x;

    // ---- job decode (64 rows per CTA) ----
    int wsel;
    const float* A;
    float* C;
    if (phase) {
        wsel = 3; A = attnA + (size_t)blk * 64 * E_; C = outC + (size_t)blk * 64 * E_;
    } else if (blk < 512) {
        wsel = 1; A = zoff + (size_t)blk * 64 * E_;        C = g_Koff + (size_t)blk * 64 * E_;
    } else if (blk < 1024) {
        wsel = 2; A = zoff + (size_t)(blk-512) * 64 * E_;  C = g_Voff + (size_t)(blk-512) * 64 * E_;
    } else if (blk < 1280) {
        wsel = 1; A = zon + (size_t)(blk-1024) * 64 * E_;  C = g_Kon + (size_t)(blk-1024) * 64 * E_;
    } else if (blk < 1536) {
        wsel = 2; A = zon + (size_t)(blk-1280) * 64 * E_;  C = g_Von + (size_t)(blk-1280) * 64 * E_;
    } else {
        wsel = 0; A = lat + (size_t)(blk-1536) * 64 * E_;  C = g_Q + (size_t)(blk-1536) * 64 * E_;
    }

    // ---- load packed W hi/lo into padded smem ----
    {
        const float4* srcH = (const float4*)g_Wp[wsel][0];
        const float4* srcL = (const float4*)g_Wp[wsel][1];
#pragma unroll
        for (int i = tid; i < 2048; i += 256) {
            int row = i >> 5;
            int c4  = i & 31;
            *(float4*)&sw[row*WROW + c4*4]        = srcH[i];
            *(float4*)&sw[8704 + row*WROW + c4*4] = srcL[i];
        }
    }
    __syncthreads();

    // ---- warp tiling: 8 warps = 4 (M) x 2 (N); warp tile 16x64 ----
    const int wid  = tid >> 5;
    const int lane = tid & 31;
    const int m0 = (wid & 3) * 16;
    const int n0 = (wid >> 2) * 64;
    const int g = lane >> 2;             // 0..7
    const int c = lane & 3;              // 0..3

    float acc[8][4];
#pragma unroll
    for (int i = 0; i < 8; i++)
#pragma unroll
        for (int j = 0; j < 4; j++) acc[i][j] = 0.f;

#pragma unroll
    for (int kc = 0; kc < 8; kc++) {
        const int k0 = kc * 16;
        const float* ar = A + (m0 + g) * E_ + k0 + 2*c;
        float2 x0 = *(const float2*)ar;
        float2 x1 = *(const float2*)(ar + 8*E_);
        float2 x2 = *(const float2*)(ar + 8);
        float2 x3 = *(const float2*)(ar + 8*E_ + 8);
        uint32_t ah[4], al[4];
        ah[0] = pk2(x0.x, x0.y);  al[0] = pk2(resid(x0.x), resid(x0.y));
        ah[1] = pk2(x1.x, x1.y);  al[1] = pk2(resid(x1.x), resid(x1.y));
        ah[2] = pk2(x2.x, x2.y);  al[2] = pk2(resid(x2.x), resid(x2.y));
        ah[3] = pk2(x3.x, x3.y);  al[3] = pk2(resid(x3.x), resid(x3.y));

        const int brow = kc * 8 + c;
#pragma unroll
        for (int nt = 0; nt < 8; nt++) {
            int col = n0 + nt*8 + g;
            uint32_t bh0 = sw[brow*WROW + col];
            uint32_t bh1 = sw[(brow+4)*WROW + col];
            uint32_t bl0 = sw[8704 + brow*WROW + col];
            uint32_t bl1 = sw[8704 + (brow+4)*WROW + col];
            mma16816(acc[nt], ah, bh0, bh1);
            mma16816(acc[nt], ah, bl0, bl1);
            mma16816(acc[nt], al, bh0, bh1);
        }
    }

    // ---- epilogue ----
#pragma unroll
    for (int nt = 0; nt < 8; nt++) {
        int colb = n0 + nt*8 + 2*c;
        *(float2*)&C[(m0 + g) * E_ + colb]     = make_float2(acc[nt][0], acc[nt][1]);
        *(float2*)&C[(m0 + g + 8) * E_ + colb] = make_float2(acc[nt][2], acc[nt][3]);
    }
}

// ---------------- Stage 4: per-bucket attention (1 warp / bucket) -----------
__global__ void __launch_bounds__(128) attn_kernel(const int* __restrict__ ign_p) {
    __shared__ int mem[4][CAP_];
    const int warp = threadIdx.x >> 5;
    const int lane = threadIdx.x & 31;
    const int n = blockIdx.x * 4 + warp;
    const int ign = *ign_p;

    int c = min(g_counts[n], CAP_);
    if (lane < c) mem[warp][lane] = g_members[n*CAP_ + lane];
    __syncwarp();
    if (lane == 0 && c > 1) {           // deterministic order
        int* a = mem[warp];
        for (int i = 1; i < c; i++) {
            int key = a[i]; int j = i - 1;
            while (j >= 0 && a[j] > key) { a[j+1] = a[j]; j--; }
            a[j+1] = key;
        }
    }
    __syncwarp();

    const int s = n & (S_ - 1);
    float4 q = *(const float4*)&g_Q[s*E_ + lane*4];

    // pointer for patch p (members first, then on-grid/fake)
    const float* klast = ign ? g_Kfake : &g_Kon[n * E_];
    const float* vlast = ign ? g_Vfake : &g_Von[n * E_];

    float m = -INFINITY, lsum = 0.f;
    float4 acc = make_float4(0.f, 0.f, 0.f, 0.f);

    // depth-1 prefetch of K/V rows
    const float* kr = (c > 0) ? &g_Koff[(size_t)mem[warp][0] * E_] : klast;
    const float* vr = (c > 0) ? &g_Voff[(size_t)mem[warp][0] * E_] : vlast;
    float4 kk = *(const float4*)&kr[lane*4];
    float4 vv = *(const float4*)&vr[lane*4];

    for (int p = 0; p <= c; p++) {
        float4 kc = kk, vc = vv;
        if (p < c) {
            const float *kn, *vn;
            if (p + 1 < c) {
                int t = mem[warp][p+1];
                kn = &g_Koff[(size_t)t * E_];
                vn = &g_Voff[(size_t)t * E_];
            } else {
                kn = klast; vn = vlast;
            }
            kk = *(const float4*)&kn[lane*4];
            vv = *(const float4*)&vn[lane*4];
        }
        float d = q.x*kc.x + q.y*kc.y + q.z*kc.z + q.w*kc.w;
        d += __shfl_xor_sync(0xffffffffu, d, 1);
        d += __shfl_xor_sync(0xffffffffu, d, 2);   // head-group (4 lanes) sum
        float sc = d * 0.25f;                      // 1/sqrt(DH=16)
        float mn = fmaxf(m, sc);
        float corr = expf(m - mn);
        float w = expf(sc - mn);
        lsum = lsum * corr + w;
        acc.x = acc.x*corr + w*vc.x;
        acc.y = acc.y*corr + w*vc.y;
        acc.z = acc.z*corr + w*vc.z;
        acc.w = acc.w*corr + w*vc.w;
        m = mn;
    }
    float inv = 1.0f / lsum;
    float4 o = make_float4(acc.x*inv, acc.y*inv, acc.z*inv, acc.w*inv);
    *(float4*)&g_attn[n*E_ + lane*4] = o;
}

// ---------------- launcher ---------------------------------------------------
extern "C" void kernel_launch(void* const* d_in, const int* in_sizes, int n_in,
                              void* d_out, int out_size) {
    const float* xoff = (const float*)d_in[0];
    const float* xon  = (const float*)d_in[1];
    const float* zoff = (const float*)d_in[2];
    const float* zon  = (const float*)d_in[3];
    const float* lat  = (const float*)d_in[4];
    const float* fake = (const float*)d_in[5];
    const float* Wq   = (const float*)d_in[6];
    const float* Wk   = (const float*)d_in[7];
    const float* Wv   = (const float*)d_in[8];
    const float* Wo   = (const float*)d_in[9];
    const int*   ign  = (const int*)d_in[10];
    float* out = (float*)d_out;

    float* pAttn;
    int* pCounts;
    cudaGetSymbolAddress((void**)&pAttn, g_attn);
    cudaGetSymbolAddress((void**)&pCounts, g_counts);

    cudaFuncSetAttribute(gemm_mma,
                         cudaFuncAttributeMaxDynamicSharedMemorySize, DSMEM_BYTES);

    cudaMemsetAsync(pCounts, 0, NB_ * sizeof(int));
    // fused prep: weight split (4) + bucketize (128) + fake proj (8)
    prep_kernel<<<140, 256>>>(Wq, Wk, Wv, Wo, xoff, xon, fake);

    // fused K/V/Q projections: 1600 CTAs of 64 rows each
    gemm_mma<<<1600, 256, DSMEM_BYTES>>>(zoff, zon, lat, nullptr, nullptr, 0);

    attn_kernel<<<NB_ / 4, 128>>>(ign);

    // output projection: attn @ Wo -> out (256 CTAs)
    gemm_mma<<<256, 256, DSMEM_BYTES>>>(nullptr, nullptr, nullptr, pAttn, out, 1);
}